// round 14
// baseline (speedup 1.0000x reference)
#include <cuda_runtime.h>
#include <cuda_bf16.h>
#include <cstdint>
#include <math.h>

#define MM   16          // B*T
#define NN   5000
#define DIN  64
#define EE   80000
#define HC   128
#define E2   (EE + NN)   // 85000 with self loops
#define ROWS (MM * NN)   // 80000

// ---------------- scratch (no allocations allowed) ----------------
// feature buffers are NODE-major: row = n*MM + m
__device__ float g_xl[ROWS * HC];   // 41 MB
__device__ float g_xr[ROWS * HC];
__device__ float g_h [ROWS * HC];   // layer-1 output (node-major)
__device__ int   g_cnt[NN];
__device__ float g_wsum[NN];
__device__ int   g_rowoff[NN + 1];
__device__ int   g_fill[NN];
__device__ float g_selfw[NN];
__device__ int2  g_epk[E2];         // {src, bitcast(weight)}
// pre-split weights: [K x 256] = [Wl | Wr] in bf16 hi/lo
__device__ __nv_bfloat16 g_W1hi[DIN * 256], g_W1lo[DIN * 256];
__device__ __nv_bfloat16 g_W2hi[HC * 256],  g_W2lo[HC * 256];

// ---------------- preprocessing ----------------
__global__ void k_zero() {
    int i = blockIdx.x * blockDim.x + threadIdx.x;
    if (i < NN) { g_cnt[i] = 0; g_wsum[i] = 0.f; }
}

__global__ void k_deg(const int* __restrict__ ei, const float* __restrict__ ew) {
    int e = blockIdx.x * blockDim.x + threadIdx.x;
    if (e < EE) {
        int d = ei[EE + e];
        atomicAdd(&g_cnt[d], 1);
        atomicAdd(&g_wsum[d], ew[e]);
    }
}

// one block, 1024 threads: exclusive scan of (deg+1), self-loop weights
__global__ void k_scan() {
    __shared__ int sums[1024];
    int tid = threadIdx.x;
    int base = tid * 5;
    int loc[5];
    int s = 0;
#pragma unroll
    for (int j = 0; j < 5; j++) {
        int i = base + j;
        int d = (i < NN) ? (g_cnt[i] + 1) : 0;   // +1 for self loop
        loc[j] = s;
        s += d;
    }
    sums[tid] = s;
    __syncthreads();
    for (int off = 1; off < 1024; off <<= 1) {
        int v = (tid >= off) ? sums[tid - off] : 0;
        __syncthreads();
        sums[tid] += v;
        __syncthreads();
    }
    int excl = (tid == 0) ? 0 : sums[tid - 1];
#pragma unroll
    for (int j = 0; j < 5; j++) {
        int i = base + j;
        if (i < NN) {
            int o = excl + loc[j];
            g_rowoff[i] = o;
            g_fill[i]   = o;
            int c = g_cnt[i];
            g_selfw[i] = (c > 0) ? (g_wsum[i] / (float)c) : 0.f;
        }
    }
    if (tid == 1023) g_rowoff[NN] = sums[1023];
}

__global__ void k_scatter(const int* __restrict__ ei, const float* __restrict__ ew) {
    int i = blockIdx.x * blockDim.x + threadIdx.x;
    if (i < EE) {
        int d = ei[EE + i];
        int p = atomicAdd(&g_fill[d], 1);
        g_epk[p] = make_int2(ei[i], __float_as_int(ew[i]));
    } else if (i < E2) {
        int n = i - EE;
        int p = atomicAdd(&g_fill[n], 1);
        g_epk[p] = make_int2(n, __float_as_int(g_selfw[n]));
    }
}

// split [Wl | Wr] (each K x 128 fp32) into bf16 hi/lo [K x 256]
__global__ void k_wsplit(const float* __restrict__ Wl, const float* __restrict__ Wr,
                         __nv_bfloat16* __restrict__ hi, __nv_bfloat16* __restrict__ lo,
                         int total) {
    int i = blockIdx.x * blockDim.x + threadIdx.x;
    if (i >= total) return;
    int k = i >> 8;
    int n = i & 255;
    float v = (n < 128) ? Wl[(size_t)k * 128 + n] : Wr[(size_t)k * 128 + (n - 128)];
    __nv_bfloat16 h = __float2bfloat16(v);
    hi[i] = h;
    lo[i] = __float2bfloat16(v - __bfloat162float(h));
}

// ---------------- tensor-core helpers ----------------
__device__ __forceinline__ void ldsm4(unsigned* r, unsigned addr) {
    asm volatile("ldmatrix.sync.aligned.m8n8.x4.shared.b16 {%0,%1,%2,%3}, [%4];"
        : "=r"(r[0]), "=r"(r[1]), "=r"(r[2]), "=r"(r[3]) : "r"(addr));
}
__device__ __forceinline__ void ldsm4t(unsigned* r, unsigned addr) {
    asm volatile("ldmatrix.sync.aligned.m8n8.x4.trans.shared.b16 {%0,%1,%2,%3}, [%4];"
        : "=r"(r[0]), "=r"(r[1]), "=r"(r[2]), "=r"(r[3]) : "r"(addr));
}
__device__ __forceinline__ void mma_bf16(float* c, const unsigned* a, const unsigned* b) {
    asm volatile(
        "mma.sync.aligned.m16n8k16.row.col.f32.bf16.bf16.f32 "
        "{%0,%1,%2,%3}, {%4,%5,%6,%7}, {%8,%9}, {%0,%1,%2,%3};"
        : "+f"(c[0]), "+f"(c[1]), "+f"(c[2]), "+f"(c[3])
        : "r"(a[0]), "r"(a[1]), "r"(a[2]), "r"(a[3]), "r"(b[0]), "r"(b[1]));
}
__device__ __forceinline__ void bsplit(float x, __nv_bfloat16& h, __nv_bfloat16& l) {
    h = __float2bfloat16(x);
    l = __float2bfloat16(x - __bfloat162float(h));
}
__device__ __forceinline__ float lrelu(float t) { return fmaxf(t, 0.2f * t); }

// ---------------- projections: [xl | xr] = A @ [Wl | Wr] ----------------
// Tensor-core GEMM, bf16 2-term split (3 MMAs: hh + hl + lh) ~= fp32 accuracy.
// Block: 64 rows x 256 cols, 256 threads (8 warps). Warp: 32 rows x 64 cols
// (two 16-row groups share ALL B fragments -> MMA:LDSM ratio 4.0).
// MAP==1: A rows are (m*NN+n) (raw x) -> output row n*MM+m. IN_H: read g_h.
#define ASTR 40
#define BSTR 264
template <int K, int MAP, int IN_H>
__global__ void __launch_bounds__(256) k_gemm(const float* __restrict__ Ain,
                                              const __nv_bfloat16* __restrict__ Whi,
                                              const __nv_bfloat16* __restrict__ Wlo) {
    __shared__ __nv_bfloat16 As_hi[64 * ASTR];
    __shared__ __nv_bfloat16 As_lo[64 * ASTR];
    __shared__ __nv_bfloat16 Bs_hi[32 * BSTR];
    __shared__ __nv_bfloat16 Bs_lo[32 * BSTR];

    const float* __restrict__ A = IN_H ? (const float*)g_h : Ain;

    const int tid  = threadIdx.x;
    const int lane = tid & 31;
    const int w    = tid >> 5;
    const int mt   = w & 1;        // m-half: rows mt*32..+31 of the 64
    const int nq   = w >> 1;       // n-quarter: cols nq*64..+63 of the 256
    const int row0 = blockIdx.x * 64;

    const unsigned ah_base = (unsigned)__cvta_generic_to_shared(As_hi);
    const unsigned al_base = (unsigned)__cvta_generic_to_shared(As_lo);
    const unsigned bh_base = (unsigned)__cvta_generic_to_shared(Bs_hi);
    const unsigned bl_base = (unsigned)__cvta_generic_to_shared(Bs_lo);

    float acc[2][8][4];
#pragma unroll
    for (int g = 0; g < 2; g++)
#pragma unroll
        for (int j = 0; j < 8; j++)
#pragma unroll
            for (int q = 0; q < 4; q++) acc[g][j][q] = 0.f;

    // staging maps
    const int sar = tid >> 2;            // A row 0..63
    const int sak = (tid & 3) * 8;       // A k-offset (2 float4)
    const unsigned a_row = (unsigned)(mt * 32 + (lane & 15));
    const unsigned a_coladd = (unsigned)((lane >> 4) << 3);
    const int bk_row = (lane & 7) + ((lane >> 3) & 1) * 8;
    const int b_nadd = (lane >> 4) << 3;

    for (int kc = 0; kc < K; kc += 32) {
        // ---- stage A chunk 64x32, split hi/lo (2 float4 per thread) ----
#pragma unroll
        for (int rep = 0; rep < 2; rep++) {
            float4 v = *(const float4*)&A[(size_t)(row0 + sar) * K + kc + sak + rep * 4];
            __nv_bfloat16 h0, l0, h1, l1, h2, l2, h3, l3;
            bsplit(v.x, h0, l0); bsplit(v.y, h1, l1);
            bsplit(v.z, h2, l2); bsplit(v.w, h3, l3);
            __nv_bfloat16* ph = &As_hi[sar * ASTR + sak + rep * 4];
            __nv_bfloat16* pl = &As_lo[sar * ASTR + sak + rep * 4];
            ph[0] = h0; ph[1] = h1; ph[2] = h2; ph[3] = h3;
            pl[0] = l0; pl[1] = l1; pl[2] = l2; pl[3] = l3;
        }
        // ---- stage B chunk 32 x 256: pure 16-byte copies of pre-split bf16 ----
#pragma unroll
        for (int i = 0; i < 8; i++) {
            int idx = tid + i * 256;     // 0..2047 uint4 slots
            int arr = idx >> 10;         // 0: hi, 1: lo
            int rem = idx & 1023;
            int k   = rem >> 5;          // 0..31
            int c8  = (rem & 31) * 8;    // 0..248
            const __nv_bfloat16* src = (arr ? Wlo : Whi) + (size_t)(kc + k) * 256 + c8;
            __nv_bfloat16* dst = (arr ? Bs_lo : Bs_hi) + k * BSTR + c8;
            *(uint4*)dst = *(const uint4*)src;
        }
        __syncthreads();

        // ---- compute: 2 k16 steps ----
#pragma unroll
        for (int kk = 0; kk < 32; kk += 16) {
            unsigned ah[2][4], al[2][4];
#pragma unroll
            for (int g = 0; g < 2; g++) {
                unsigned aoff = ((a_row + g * 16) * ASTR + (unsigned)kk + a_coladd) * 2u;
                ldsm4(ah[g], ah_base + aoff);
                ldsm4(al[g], al_base + aoff);
            }

            unsigned bh[16], bl[16];
#pragma unroll
            for (int t2 = 0; t2 < 4; t2++) {
                unsigned boff = ((unsigned)((kk + bk_row) * BSTR + nq * 64 + t2 * 16 + b_nadd)) * 2u;
                ldsm4t(&bh[t2 * 4], bh_base + boff);
                ldsm4t(&bl[t2 * 4], bl_base + boff);
            }
#pragma unroll
            for (int j = 0; j < 8; j++) {
                const unsigned* bhj = &bh[(j >> 1) * 4 + (j & 1) * 2];
                const unsigned* blj = &bl[(j >> 1) * 4 + (j & 1) * 2];
#pragma unroll
                for (int g = 0; g < 2; g++) {
                    mma_bf16(acc[g][j], ah[g], bhj);   // hi*hi
                    mma_bf16(acc[g][j], ah[g], blj);   // hi*lo
                    mma_bf16(acc[g][j], al[g], bhj);   // lo*hi
                }
            }
        }
        __syncthreads();
    }

    // ---- epilogue ----
    int lcol = 2 * (lane & 3);
#pragma unroll
    for (int g = 0; g < 2; g++) {
        int lrow = mt * 32 + g * 16 + (lane >> 2);
#pragma unroll
        for (int half = 0; half < 2; half++) {
            int r = row0 + lrow + half * 8;
            int orow;
            if (MAP == 1) {
                int m = r / NN;
                int n = r - m * NN;
                orow  = n * MM + m;
            } else {
                orow = r;
            }
#pragma unroll
            for (int j = 0; j < 8; j++) {
                int c = nq * 64 + j * 8 + lcol;
                float* buf = (c < 128) ? g_xl : g_xr;
                int cc = (c < 128) ? c : c - 128;
                *(float2*)&buf[(size_t)orow * HC + cc] =
                    make_float2(acc[g][j][half * 2], acc[g][j][half * 2 + 1]);
            }
        }
    }
}

// ---------------- fused edge kernel: gather + online softmax + aggregate ----------------
// One block per dst (grid NN, 8 warps). Each warp handles TWO m's:
// lanes 0-15 -> m = 2*warp, lanes 16-31 -> m = 2*warp+1.
// Each lane owns 8 contiguous channels; 3-step shuffle reduction; dual-state.
template <int LAYER2>
__global__ void __launch_bounds__(256) k_edge(const float* __restrict__ We,
                                              const float* __restrict__ att,
                                              const float* __restrict__ bias,
                                              float* __restrict__ out) {
    int warp = threadIdx.x >> 5;
    int lane = threadIdx.x & 31;
    int dst  = blockIdx.x;
    int m    = (warp << 1) | (lane >> 4);
    int ch   = (lane & 15) << 3;      // channel base, 8 channels per lane

    float xi[8], we[8], at[8];
    {
        const float* p = &g_xr[(size_t)(dst * MM + m) * HC + ch];
        *(float4*)&xi[0] = *(const float4*)p;
        *(float4*)&xi[4] = *(const float4*)(p + 4);
        *(float4*)&we[0] = *(const float4*)&We[ch];
        *(float4*)&we[4] = *(const float4*)&We[ch + 4];
        *(float4*)&at[0] = *(const float4*)&att[ch];
        *(float4*)&at[4] = *(const float4*)&att[ch + 4];
    }

    float accA[8], accB[8];
#pragma unroll
    for (int i = 0; i < 8; i++) { accA[i] = 0.f; accB[i] = 0.f; }
    float mxA = -1e30f, dnA = 0.f;
    float mxB = -1e30f, dnB = 0.f;

    int beg = g_rowoff[dst];
    int end = g_rowoff[dst + 1];

    int j = beg;
    for (; j + 1 < end; j += 2) {
        int2 eA = g_epk[j];
        int2 eB = g_epk[j + 1];
        float wA = __int_as_float(eA.y);
        float wB = __int_as_float(eB.y);
        float xjA[8], xjB[8];
        {
            const float* pA = &g_xl[(size_t)(eA.x * MM + m) * HC + ch];
            const float* pB = &g_xl[(size_t)(eB.x * MM + m) * HC + ch];
            *(float4*)&xjA[0] = *(const float4*)pA;
            *(float4*)&xjA[4] = *(const float4*)(pA + 4);
            *(float4*)&xjB[0] = *(const float4*)pB;
            *(float4*)&xjB[4] = *(const float4*)(pB + 4);
        }

        float pA = 0.f, pB = 0.f;
#pragma unroll
        for (int i = 0; i < 8; i++) {
            pA = fmaf(lrelu(fmaf(wA, we[i], xi[i] + xjA[i])), at[i], pA);
            pB = fmaf(lrelu(fmaf(wB, we[i], xi[i] + xjB[i])), at[i], pB);
        }
#pragma unroll
        for (int off = 1; off <= 4; off <<= 1) {
            pA += __shfl_xor_sync(0xffffffffu, pA, off);
            pB += __shfl_xor_sync(0xffffffffu, pB, off);
        }

        float nmA = fmaxf(mxA, pA);
        float nmB = fmaxf(mxB, pB);
        float scA = __expf(mxA - nmA);
        float scB = __expf(mxB - nmB);
        float eA_ = __expf(pA - nmA);
        float eB_ = __expf(pB - nmB);
        dnA = dnA * scA + eA_;
        dnB = dnB * scB + eB_;
#pragma unroll
        for (int i = 0; i < 8; i++) {
            accA[i] = fmaf(eA_, xjA[i], accA[i] * scA);
            accB[i] = fmaf(eB_, xjB[i], accB[i] * scB);
        }
        mxA = nmA;  mxB = nmB;
    }
    if (j < end) {
        int2 eA = g_epk[j];
        float wA = __int_as_float(eA.y);
        float xjA[8];
        const float* pAp = &g_xl[(size_t)(eA.x * MM + m) * HC + ch];
        *(float4*)&xjA[0] = *(const float4*)pAp;
        *(float4*)&xjA[4] = *(const float4*)(pAp + 4);
        float pA = 0.f;
#pragma unroll
        for (int i = 0; i < 8; i++)
            pA = fmaf(lrelu(fmaf(wA, we[i], xi[i] + xjA[i])), at[i], pA);
#pragma unroll
        for (int off = 1; off <= 4; off <<= 1)
            pA += __shfl_xor_sync(0xffffffffu, pA, off);
        float nmA = fmaxf(mxA, pA);
        float scA = __expf(mxA - nmA);
        float eA_ = __expf(pA - nmA);
        dnA = dnA * scA + eA_;
#pragma unroll
        for (int i = 0; i < 8; i++)
            accA[i] = fmaf(eA_, xjA[i], accA[i] * scA);
        mxA = nmA;
    }

    // merge state B into A (B may be empty: dnB=0 contributes nothing)
    float nm = fmaxf(mxA, mxB);
    float sA = __expf(mxA - nm);
    float sB = __expf(mxB - nm);
    float dn = dnA * sA + dnB * sB;
    float inv = 1.f / (dn + 1e-16f);

    float o[8];
#pragma unroll
    for (int i = 0; i < 8; i++) {
        float v = (accA[i] * sA + accB[i] * sB) * inv + bias[ch + i];
        o[i] = (v > 0.f) ? v : (__expf(v) - 1.f);   // ELU
    }

    float* dstp = LAYER2 ? &out[(size_t)(m * NN + dst) * HC + ch]
                         : &g_h[(size_t)(dst * MM + m) * HC + ch];
    *(float4*)dstp       = *(float4*)&o[0];
    *(float4*)(dstp + 4) = *(float4*)&o[4];
}

// ---------------- launch ----------------
extern "C" void kernel_launch(void* const* d_in, const int* in_sizes, int n_in,
                              void* d_out, int out_size) {
    const float* x    = (const float*)d_in[0];
    const int*   ei   = (const int*)d_in[1];
    const float* ew   = (const float*)d_in[2];
    const float* Wl1  = (const float*)d_in[3];
    const float* Wr1  = (const float*)d_in[4];
    const float* att1 = (const float*)d_in[5];
    const float* We1  = (const float*)d_in[6];
    const float* b1   = (const float*)d_in[7];
    const float* Wl2  = (const float*)d_in[8];
    const float* Wr2  = (const float*)d_in[9];
    const float* att2 = (const float*)d_in[10];
    const float* We2  = (const float*)d_in[11];
    const float* b2   = (const float*)d_in[12];
    float* out = (float*)d_out;

    __nv_bfloat16 *w1hi, *w1lo, *w2hi, *w2lo;
    cudaGetSymbolAddress((void**)&w1hi, g_W1hi);
    cudaGetSymbolAddress((void**)&w1lo, g_W1lo);
    cudaGetSymbolAddress((void**)&w2hi, g_W2hi);
    cudaGetSymbolAddress((void**)&w2lo, g_W2lo);

    k_zero<<<(NN + 255) / 256, 256>>>();
    k_deg<<<(EE + 255) / 256, 256>>>(ei, ew);
    k_scan<<<1, 1024>>>();
    k_scatter<<<(E2 + 255) / 256, 256>>>(ei, ew);
    k_wsplit<<<(DIN * 256 + 255) / 256, 256>>>(Wl1, Wr1, w1hi, w1lo, DIN * 256);
    k_wsplit<<<(HC * 256 + 255) / 256, 256>>>(Wl2, Wr2, w2hi, w2lo, HC * 256);

    // layer 1
    k_gemm<DIN, 1, 0><<<ROWS / 64, 256>>>(x, w1hi, w1lo);
    k_edge<0><<<NN, 256>>>(We1, att1, b1, nullptr);

    // layer 2
    k_gemm<HC, 0, 1><<<ROWS / 64, 256>>>(nullptr, w2hi, w2lo);
    k_edge<1><<<NN, 256>>>(We2, att2, b2, out);
}

// round 15
// speedup vs baseline: 1.1902x; 1.1902x over previous
#include <cuda_runtime.h>
#include <cuda_bf16.h>
#include <cstdint>
#include <math.h>

#define MM   16          // B*T
#define NN   5000
#define DIN  64
#define EE   80000
#define HC   128
#define E2   (EE + NN)   // 85000 with self loops
#define ROWS (MM * NN)   // 80000

// ---------------- scratch (no allocations allowed) ----------------
// feature buffers are NODE-major: row = n*MM + m
__device__ float g_xl[ROWS * HC];   // 41 MB
__device__ float g_xr[ROWS * HC];
__device__ float g_h [ROWS * HC];   // layer-1 output (node-major)
__device__ int   g_cnt[NN];
__device__ float g_wsum[NN];
__device__ int   g_rowoff[NN + 1];
__device__ int   g_fill[NN];
__device__ float g_selfw[NN];
__device__ int2  g_epk[E2];         // {src, bitcast(weight)}
// pre-split weights: [K x 256] = [Wl | Wr] in bf16 hi/lo
__device__ __nv_bfloat16 g_W1hi[DIN * 256], g_W1lo[DIN * 256];
__device__ __nv_bfloat16 g_W2hi[HC * 256],  g_W2lo[HC * 256];

// ---------------- preprocessing ----------------
// fused: zero counters + pre-split both weight matrices
__global__ void k_pre(const float* __restrict__ Wl1, const float* __restrict__ Wr1,
                      const float* __restrict__ Wl2, const float* __restrict__ Wr2) {
    int i = blockIdx.x * blockDim.x + threadIdx.x;
    if (i < NN) { g_cnt[i] = 0; g_wsum[i] = 0.f; }
    if (i < DIN * 256) {
        int k = i >> 8, n = i & 255;
        float v = (n < 128) ? Wl1[(size_t)k * 128 + n] : Wr1[(size_t)k * 128 + (n - 128)];
        __nv_bfloat16 h = __float2bfloat16(v);
        g_W1hi[i] = h;
        g_W1lo[i] = __float2bfloat16(v - __bfloat162float(h));
    }
    if (i < HC * 256) {
        int k = i >> 8, n = i & 255;
        float v = (n < 128) ? Wl2[(size_t)k * 128 + n] : Wr2[(size_t)k * 128 + (n - 128)];
        __nv_bfloat16 h = __float2bfloat16(v);
        g_W2hi[i] = h;
        g_W2lo[i] = __float2bfloat16(v - __bfloat162float(h));
    }
}

__global__ void k_deg(const int* __restrict__ ei, const float* __restrict__ ew) {
    int e = blockIdx.x * blockDim.x + threadIdx.x;
    if (e < EE) {
        int d = ei[EE + e];
        atomicAdd(&g_cnt[d], 1);
        atomicAdd(&g_wsum[d], ew[e]);
    }
}

// one block, 1024 threads: exclusive scan of (deg+1), self-loop weights
__global__ void k_scan() {
    __shared__ int sums[1024];
    int tid = threadIdx.x;
    int base = tid * 5;
    int loc[5];
    int s = 0;
#pragma unroll
    for (int j = 0; j < 5; j++) {
        int i = base + j;
        int d = (i < NN) ? (g_cnt[i] + 1) : 0;   // +1 for self loop
        loc[j] = s;
        s += d;
    }
    sums[tid] = s;
    __syncthreads();
    for (int off = 1; off < 1024; off <<= 1) {
        int v = (tid >= off) ? sums[tid - off] : 0;
        __syncthreads();
        sums[tid] += v;
        __syncthreads();
    }
    int excl = (tid == 0) ? 0 : sums[tid - 1];
#pragma unroll
    for (int j = 0; j < 5; j++) {
        int i = base + j;
        if (i < NN) {
            int o = excl + loc[j];
            g_rowoff[i] = o;
            g_fill[i]   = o;
            int c = g_cnt[i];
            g_selfw[i] = (c > 0) ? (g_wsum[i] / (float)c) : 0.f;
        }
    }
    if (tid == 1023) g_rowoff[NN] = sums[1023];
}

__global__ void k_scatter(const int* __restrict__ ei, const float* __restrict__ ew) {
    int i = blockIdx.x * blockDim.x + threadIdx.x;
    if (i < EE) {
        int d = ei[EE + i];
        int p = atomicAdd(&g_fill[d], 1);
        g_epk[p] = make_int2(ei[i], __float_as_int(ew[i]));
    } else if (i < E2) {
        int n = i - EE;
        int p = atomicAdd(&g_fill[n], 1);
        g_epk[p] = make_int2(n, __float_as_int(g_selfw[n]));
    }
}

// ---------------- tensor-core helpers ----------------
__device__ __forceinline__ void ldsm4(unsigned* r, unsigned addr) {
    asm volatile("ldmatrix.sync.aligned.m8n8.x4.shared.b16 {%0,%1,%2,%3}, [%4];"
        : "=r"(r[0]), "=r"(r[1]), "=r"(r[2]), "=r"(r[3]) : "r"(addr));
}
__device__ __forceinline__ void ldsm4t(unsigned* r, unsigned addr) {
    asm volatile("ldmatrix.sync.aligned.m8n8.x4.trans.shared.b16 {%0,%1,%2,%3}, [%4];"
        : "=r"(r[0]), "=r"(r[1]), "=r"(r[2]), "=r"(r[3]) : "r"(addr));
}
__device__ __forceinline__ void mma_bf16(float* c, const unsigned* a, const unsigned* b) {
    asm volatile(
        "mma.sync.aligned.m16n8k16.row.col.f32.bf16.bf16.f32 "
        "{%0,%1,%2,%3}, {%4,%5,%6,%7}, {%8,%9}, {%0,%1,%2,%3};"
        : "+f"(c[0]), "+f"(c[1]), "+f"(c[2]), "+f"(c[3])
        : "r"(a[0]), "r"(a[1]), "r"(a[2]), "r"(a[3]), "r"(b[0]), "r"(b[1]));
}
__device__ __forceinline__ void bsplit(float x, __nv_bfloat16& h, __nv_bfloat16& l) {
    h = __float2bfloat16(x);
    l = __float2bfloat16(x - __bfloat162float(h));
}
__device__ __forceinline__ float lrelu(float t) { return fmaxf(t, 0.2f * t); }

// ---------------- projections: [xl | xr] = A @ [Wl | Wr] ----------------
// Tensor-core GEMM, bf16 2-term split (3 MMAs: hh + hl + lh) ~= fp32 accuracy.
// B comes pre-split in bf16 (g_W*hi/lo): staging is pure 16B copies, no cvt.
// Block: 32 rows x 256 cols, 256 threads (8 warps). Warp: 16 rows x 64 cols.
// MAP==1: A rows are (m*NN+n) (raw x) -> output row n*MM+m. IN_H: read g_h.
#define ASTR 40
#define BSTR 264
template <int K, int MAP, int IN_H>
__global__ void __launch_bounds__(256) k_gemm(const float* __restrict__ Ain,
                                              const __nv_bfloat16* __restrict__ Whi,
                                              const __nv_bfloat16* __restrict__ Wlo) {
    __shared__ __nv_bfloat16 As_hi[32 * ASTR];
    __shared__ __nv_bfloat16 As_lo[32 * ASTR];
    __shared__ __nv_bfloat16 Bs_hi[32 * BSTR];
    __shared__ __nv_bfloat16 Bs_lo[32 * BSTR];

    const float* __restrict__ A = IN_H ? (const float*)g_h : Ain;

    const int tid  = threadIdx.x;
    const int lane = tid & 31;
    const int w    = tid >> 5;
    const int mt   = w & 1;        // m-tile: rows mt*16..+15 of the 32
    const int nq   = w >> 1;       // n-quarter: cols nq*64..+63 of the 256
    const int row0 = blockIdx.x * 32;

    const unsigned ah_base = (unsigned)__cvta_generic_to_shared(As_hi);
    const unsigned al_base = (unsigned)__cvta_generic_to_shared(As_lo);
    const unsigned bh_base = (unsigned)__cvta_generic_to_shared(Bs_hi);
    const unsigned bl_base = (unsigned)__cvta_generic_to_shared(Bs_lo);

    float acc[8][4];
#pragma unroll
    for (int j = 0; j < 8; j++)
#pragma unroll
        for (int q = 0; q < 4; q++) acc[j][q] = 0.f;

    // staging maps
    const int sar = tid >> 3;            // A row 0..31
    const int sak = (tid & 7) * 4;       // A k-offset
    const unsigned a_row = (unsigned)(mt * 16 + (lane & 15));
    const unsigned a_coladd = (unsigned)((lane >> 4) << 3);
    const int bk_row = (lane & 7) + ((lane >> 3) & 1) * 8;
    const int b_nadd = (lane >> 4) << 3;

    for (int kc = 0; kc < K; kc += 32) {
        // ---- stage A chunk 32x32, split hi/lo ----
        {
            float4 v = *(const float4*)&A[(size_t)(row0 + sar) * K + kc + sak];
            __nv_bfloat16 h0, l0, h1, l1, h2, l2, h3, l3;
            bsplit(v.x, h0, l0); bsplit(v.y, h1, l1);
            bsplit(v.z, h2, l2); bsplit(v.w, h3, l3);
            __nv_bfloat16* ph = &As_hi[sar * ASTR + sak];
            __nv_bfloat16* pl = &As_lo[sar * ASTR + sak];
            ph[0] = h0; ph[1] = h1; ph[2] = h2; ph[3] = h3;
            pl[0] = l0; pl[1] = l1; pl[2] = l2; pl[3] = l3;
        }
        // ---- stage B chunk 32 x 256: pure 16-byte copies of pre-split bf16 ----
#pragma unroll
        for (int i = 0; i < 8; i++) {
            int idx = tid + i * 256;     // 0..2047 uint4 slots
            int arr = idx >> 10;         // 0: hi, 1: lo
            int rem = idx & 1023;
            int k   = rem >> 5;          // 0..31
            int c8  = (rem & 31) * 8;    // 0..248
            const __nv_bfloat16* src = (arr ? Wlo : Whi) + (size_t)(kc + k) * 256 + c8;
            __nv_bfloat16* dst = (arr ? Bs_lo : Bs_hi) + k * BSTR + c8;
            *(uint4*)dst = *(const uint4*)src;
        }
        __syncthreads();

        // ---- compute: 2 k16 steps ----
#pragma unroll
        for (int kk = 0; kk < 32; kk += 16) {
            unsigned ah[4], al[4];
            unsigned aoff = (a_row * ASTR + (unsigned)kk + a_coladd) * 2u;
            ldsm4(ah, ah_base + aoff);
            ldsm4(al, al_base + aoff);

            unsigned bh[16], bl[16];
#pragma unroll
            for (int t2 = 0; t2 < 4; t2++) {
                unsigned boff = ((unsigned)((kk + bk_row) * BSTR + nq * 64 + t2 * 16 + b_nadd)) * 2u;
                ldsm4t(&bh[t2 * 4], bh_base + boff);
                ldsm4t(&bl[t2 * 4], bl_base + boff);
            }
#pragma unroll
            for (int j = 0; j < 8; j++) {
                const unsigned* bhj = &bh[(j >> 1) * 4 + (j & 1) * 2];
                const unsigned* blj = &bl[(j >> 1) * 4 + (j & 1) * 2];
                mma_bf16(acc[j], ah, bhj);   // hi*hi
                mma_bf16(acc[j], ah, blj);   // hi*lo
                mma_bf16(acc[j], al, bhj);   // lo*hi
            }
        }
        __syncthreads();
    }

    // ---- epilogue ----
    int lrow = mt * 16 + (lane >> 2);
    int lcol = 2 * (lane & 3);
#pragma unroll
    for (int half = 0; half < 2; half++) {
        int r = row0 + lrow + half * 8;
        int orow;
        if (MAP == 1) {
            int m = r / NN;
            int n = r - m * NN;
            orow  = n * MM + m;
        } else {
            orow = r;
        }
#pragma unroll
        for (int j = 0; j < 8; j++) {
            int c = nq * 64 + j * 8 + lcol;
            float* buf = (c < 128) ? g_xl : g_xr;
            int cc = (c < 128) ? c : c - 128;
            *(float2*)&buf[(size_t)orow * HC + cc] =
                make_float2(acc[j][half * 2], acc[j][half * 2 + 1]);
        }
    }
}

// ---------------- fused edge kernel: gather + shifted-exp softmax + aggregate ----------------
// One block per dst (grid NN, 8 warps). Each warp handles TWO m's:
// lanes 0-15 -> m = 2*warp, lanes 16-31 -> m = 2*warp+1.
// Each lane owns 8 contiguous channels; 3-step shuffle reduction.
// Softmax: peel edge 0 (self loop guarantees deg>=1), use its logit as the
// fixed shift; accumulate exp(p - p0) directly -> no max tracking, no rescale,
// ONE exp per edge. Shift-invariance makes this exact softmax.
template <int LAYER2>
__global__ void __launch_bounds__(256) k_edge(const float* __restrict__ We,
                                              const float* __restrict__ att,
                                              const float* __restrict__ bias,
                                              float* __restrict__ out) {
    int warp = threadIdx.x >> 5;
    int lane = threadIdx.x & 31;
    int dst  = blockIdx.x;
    int m    = (warp << 1) | (lane >> 4);
    int ch   = (lane & 15) << 3;      // channel base, 8 channels per lane

    float xi[8], we[8], at[8];
    {
        const float* p = &g_xr[(size_t)(dst * MM + m) * HC + ch];
        *(float4*)&xi[0] = *(const float4*)p;
        *(float4*)&xi[4] = *(const float4*)(p + 4);
        *(float4*)&we[0] = *(const float4*)&We[ch];
        *(float4*)&we[4] = *(const float4*)&We[ch + 4];
        *(float4*)&at[0] = *(const float4*)&att[ch];
        *(float4*)&at[4] = *(const float4*)&att[ch + 4];
    }

    int beg = g_rowoff[dst];
    int end = g_rowoff[dst + 1];   // end - beg >= 1 (self loop)

    // ---- peel edge 0: defines the shift; contributes exp(0)=1 ----
    float acc[8];
    float off, dn = 1.f;
    {
        int2 e0 = g_epk[beg];
        float w0 = __int_as_float(e0.y);
        const float* p0 = &g_xl[(size_t)(e0.x * MM + m) * HC + ch];
        float xj[8];
        *(float4*)&xj[0] = *(const float4*)p0;
        *(float4*)&xj[4] = *(const float4*)(p0 + 4);
        float p = 0.f;
#pragma unroll
        for (int i = 0; i < 8; i++) {
            p = fmaf(lrelu(fmaf(w0, we[i], xi[i] + xj[i])), at[i], p);
            acc[i] = xj[i];
        }
#pragma unroll
        for (int o2 = 1; o2 <= 4; o2 <<= 1)
            p += __shfl_xor_sync(0xffffffffu, p, o2);
        off = p;
    }

    // ---- dual-unrolled main loop ----
    int j = beg + 1;
    for (; j + 1 < end; j += 2) {
        int2 eA = g_epk[j];
        int2 eB = g_epk[j + 1];
        float wA = __int_as_float(eA.y);
        float wB = __int_as_float(eB.y);
        float xjA[8], xjB[8];
        {
            const float* pA = &g_xl[(size_t)(eA.x * MM + m) * HC + ch];
            const float* pB = &g_xl[(size_t)(eB.x * MM + m) * HC + ch];
            *(float4*)&xjA[0] = *(const float4*)pA;
            *(float4*)&xjA[4] = *(const float4*)(pA + 4);
            *(float4*)&xjB[0] = *(const float4*)pB;
            *(float4*)&xjB[4] = *(const float4*)(pB + 4);
        }

        float pA = 0.f, pB = 0.f;
#pragma unroll
        for (int i = 0; i < 8; i++) {
            pA = fmaf(lrelu(fmaf(wA, we[i], xi[i] + xjA[i])), at[i], pA);
            pB = fmaf(lrelu(fmaf(wB, we[i], xi[i] + xjB[i])), at[i], pB);
        }
#pragma unroll
        for (int o2 = 1; o2 <= 4; o2 <<= 1) {
            pA += __shfl_xor_sync(0xffffffffu, pA, o2);
            pB += __shfl_xor_sync(0xffffffffu, pB, o2);
        }

        float eA_ = __expf(pA - off);
        float eB_ = __expf(pB - off);
        dn += eA_ + eB_;
#pragma unroll
        for (int i = 0; i < 8; i++)
            acc[i] = fmaf(eB_, xjB[i], fmaf(eA_, xjA[i], acc[i]));
    }
    if (j < end) {
        int2 eA = g_epk[j];
        float wA = __int_as_float(eA.y);
        float xjA[8];
        const float* pAp = &g_xl[(size_t)(eA.x * MM + m) * HC + ch];
        *(float4*)&xjA[0] = *(const float4*)pAp;
        *(float4*)&xjA[4] = *(const float4*)(pAp + 4);
        float pA = 0.f;
#pragma unroll
        for (int i = 0; i < 8; i++)
            pA = fmaf(lrelu(fmaf(wA, we[i], xi[i] + xjA[i])), at[i], pA);
#pragma unroll
        for (int o2 = 1; o2 <= 4; o2 <<= 1)
            pA += __shfl_xor_sync(0xffffffffu, pA, o2);
        float eA_ = __expf(pA - off);
        dn += eA_;
#pragma unroll
        for (int i = 0; i < 8; i++)
            acc[i] = fmaf(eA_, xjA[i], acc[i]);
    }

    float inv = 1.f / dn;   // dn >= 1, EPS negligible
    float o[8];
#pragma unroll
    for (int i = 0; i < 8; i++) {
        float v = acc[i] * inv + bias[ch + i];
        o[i] = (v > 0.f) ? v : (__expf(v) - 1.f);   // ELU
    }

    float* dstp = LAYER2 ? &out[(size_t)(m * NN + dst) * HC + ch]
                         : &g_h[(size_t)(dst * MM + m) * HC + ch];
    *(float4*)dstp       = *(float4*)&o[0];
    *(float4*)(dstp + 4) = *(float4*)&o[4];
}

// ---------------- launch ----------------
extern "C" void kernel_launch(void* const* d_in, const int* in_sizes, int n_in,
                              void* d_out, int out_size) {
    const float* x    = (const float*)d_in[0];
    const int*   ei   = (const int*)d_in[1];
    const float* ew   = (const float*)d_in[2];
    const float* Wl1  = (const float*)d_in[3];
    const float* Wr1  = (const float*)d_in[4];
    const float* att1 = (const float*)d_in[5];
    const float* We1  = (const float*)d_in[6];
    const float* b1   = (const float*)d_in[7];
    const float* Wl2  = (const float*)d_in[8];
    const float* Wr2  = (const float*)d_in[9];
    const float* att2 = (const float*)d_in[10];
    const float* We2  = (const float*)d_in[11];
    const float* b2   = (const float*)d_in[12];
    float* out = (float*)d_out;

    __nv_bfloat16 *w1hi, *w1lo, *w2hi, *w2lo;
    cudaGetSymbolAddress((void**)&w1hi, g_W1hi);
    cudaGetSymbolAddress((void**)&w1lo, g_W1lo);
    cudaGetSymbolAddress((void**)&w2hi, g_W2hi);
    cudaGetSymbolAddress((void**)&w2lo, g_W2lo);

    k_pre<<<(HC * 256 + 255) / 256, 256>>>(Wl1, Wr1, Wl2, Wr2);
    k_deg<<<(EE + 255) / 256, 256>>>(ei, ew);
    k_scan<<<1, 1024>>>();
    k_scatter<<<(E2 + 255) / 256, 256>>>(ei, ew);

    // layer 1
    k_gemm<DIN, 1, 0><<<ROWS / 32, 256>>>(x, w1hi, w1lo);
    k_edge<0><<<NN, 256>>>(We1, att1, b1, nullptr);

    // layer 2
    k_gemm<HC, 0, 1><<<ROWS / 32, 256>>>(nullptr, w2hi, w2lo);
    k_edge<1><<<NN, 256>>>(We2, att2, b2, out);
}